// round 3
// baseline (speedup 1.0000x reference)
#include <cuda_runtime.h>
#include <math.h>
#include <stdint.h>

// ---------------------------------------------------------------------------
// Problem constants
// ---------------------------------------------------------------------------
#define B_SZ   8
#define C_IN   64
#define HID    256
#define H_SZ   256
#define W_SZ   256

// Tile: 4 rows x 32 cols = 128 pixels per CTA
#define TROWS  4
#define TCOLS  32
#define TPIX   128
#define THREADS 512

// hid chunking: 2 chunks of 128
#define CH_HID 128

// smem pitches (floats)
#define W1_PITCH 260   // w1_s[c][hid]
#define X_PITCH  132   // x_s[c][pix]
#define H_PITCH  132   // h_s[hid_local][pix]
#define W2C_PITCH 68   // w2c_s[hid_local][c]

// smem layout (byte offsets) -- all 16B aligned
#define OFF_W1  0
#define SZ_W1   (64 * W1_PITCH * 4)            // 66560
#define OFF_X   (OFF_W1 + SZ_W1)               // 66560
#define SZ_X    (64 * X_PITCH * 4)             // 33792
#define OFF_H   (OFF_X + SZ_X)                 // 100352
#define SZ_H    (128 * H_PITCH * 4)            // 67584
#define OFF_W2C (OFF_H + SZ_H)                 // 167936
#define SZ_W2C  (128 * W2C_PITCH * 4)          // 34816
#define OFF_B1  (OFF_W2C + SZ_W2C)             // 202752
#define OFF_B2  (OFF_B1 + 256 * 4)             // 203776
#define SMEM_BYTES (OFF_B2 + 64 * 4)           // 204032

typedef unsigned long long ull;

// ---------------------------------------------------------------------------
// f32x2 packed-math helpers (Blackwell FFMA2 path)
// ---------------------------------------------------------------------------
__device__ __forceinline__ ull fma2(ull a, ull b, ull c) {
    ull d;
    asm("fma.rn.f32x2 %0, %1, %2, %3;" : "=l"(d) : "l"(a), "l"(b), "l"(c));
    return d;
}
__device__ __forceinline__ ull add2(ull a, ull b) {
    ull d;
    asm("add.rn.f32x2 %0, %1, %2;" : "=l"(d) : "l"(a), "l"(b));
    return d;
}
__device__ __forceinline__ ull pack2(float x) {
    ull d;
    asm("mov.b64 %0, {%1, %1};" : "=l"(d) : "f"(x));
    return d;
}
__device__ __forceinline__ void unpack2(ull v, float& lo, float& hi) {
    asm("mov.b64 {%0, %1}, %2;" : "=f"(lo), "=f"(hi) : "l"(v));
}

// ---------------------------------------------------------------------------
// Per-channel 16x16 Fourier-mix matrix, precomputed each launch.
// ---------------------------------------------------------------------------
__device__ float g_M[64 * 256];

__global__ void build_mix_kernel(const float* __restrict__ cw) {
    const int c   = blockIdx.x;      // 0..63
    const int t   = threadIdx.x;     // 0..255
    const int in  = t >> 4;
    const int out = t & 15;
    const int s  = in >> 2, tt = in & 3;
    const int p  = out >> 2, q  = out & 3;

    const float cs[4] = {1.f, 0.f, -1.f, 0.f};
    const float sn[4] = {0.f, 1.f, 0.f, -1.f};

    float tre[3] = {0.f, 0.f, 0.f};
    float tim[3] = {0.f, 0.f, 0.f};

    #pragma unroll
    for (int u = 0; u < 4; ++u) {
        const int e2 = (u * p) & 3;
        const float c2 = cs[e2], s2 = sn[e2];
        #pragma unroll
        for (int v = 0; v < 3; ++v) {
            const int e1 = (4 - ((u * s + v * tt) & 3)) & 3;
            const float yr = 0.25f * cs[e1];
            const float yi = 0.25f * sn[e1];
            const float wr = cw[((u * 3 + v) * 64 + c) * 2 + 0];
            const float wi = cw[((u * 3 + v) * 64 + c) * 2 + 1];
            const float zr = yr * wr - yi * wi;
            const float zi = yr * wi + yi * wr;
            tre[v] += zr * c2 - zi * s2;
            tim[v] += zr * s2 + zi * c2;
        }
    }

    const float sgn = (q & 1) ? -1.f : 1.f;
    const float val = 0.25f * (tre[0] + sgn * tre[2]
                               + 2.f * (tre[1] * cs[q] - tim[1] * sn[q]));
    g_M[c * 256 + out * 16 + in] = val;
}

// ---------------------------------------------------------------------------
// Main fused kernel
// ---------------------------------------------------------------------------
__device__ __forceinline__ float gelu_exact(float x) {
    return 0.5f * x * (1.f + erff(x * 0.70710678118654752440f));
}

__global__ __launch_bounds__(THREADS, 1)
void fmffn_kernel(const float* __restrict__ x,
                  const float* __restrict__ w1,
                  const float* __restrict__ b1,
                  const float* __restrict__ w2,
                  const float* __restrict__ b2,
                  float* __restrict__ out) {
    extern __shared__ float smem[];
    float* w1_s  = smem + OFF_W1  / 4;
    float* x_s   = smem + OFF_X   / 4;
    float* h_s   = smem + OFF_H   / 4;
    float* w2c_s = smem + OFF_W2C / 4;
    float* b1_s  = smem + OFF_B1  / 4;
    float* b2_s  = smem + OFF_B2  / 4;

    const int tid  = threadIdx.x;
    const int w    = tid >> 5;
    const int lane = tid & 31;
    const int b    = blockIdx.z;
    const int h0   = blockIdx.y * TROWS;
    const int w0   = blockIdx.x * TCOLS;

    // ---- GEMM1 warp/lane layout: warp tile 16 hid x 64 pix ----
    const int hg  = w >> 1;                 // 0..7
    const int pg  = w & 1;                  // 0..1
    const int hl  = lane >> 3;              // 0..3
    const int pl  = lane & 7;               // 0..7
    const int wrow = hg * 16 + hl * 4;      // hid offset within chunk (0..124)
    const int pixb = pg * 64 + pl * 8;      // pixel base (0..120)

    // ---- GEMM2 warp/lane layout: warp-pair tile 16 c x 64 pix, k split ----
    const int t2    = w >> 1;               // 0..7
    const int khalf = w & 1;                // k range half
    const int cg    = t2 >> 1;              // 0..3
    const int pg2   = t2 & 1;               // 0..1
    const int cl    = lane >> 3;            // 0..3
    const int pl2   = lane & 7;             // 0..7
    const int crow  = cg * 16 + cl * 4;     // c base (0..60)
    const int pixb2 = pg2 * 64 + pl2 * 8;   // pixel base

    // ---- prefetch FULL w2 chunk 0 into regs (128 hid x 64 c per chunk;
    //      512 threads x 16 floats = 8192 = full chunk) ----
    const int c_w2 = tid >> 3;              // 0..63
    const int h4   = (tid & 7) * 4;         // 0..28 (stride-32 groups via j)
    float4 pw2[4];
    #pragma unroll
    for (int j = 0; j < 4; ++j)
        pw2[j] = *(const float4*)&w2[c_w2 * 256 + h4 + j * 32];

    // ---- cooperative staging ----
    for (int i = tid; i < HID * C_IN; i += THREADS) {      // w1 [hid][c] -> [c][hid]
        const int hid = i >> 6, c = i & 63;
        w1_s[c * W1_PITCH + hid] = w1[i];
    }
    for (int i = tid; i < C_IN * TPIX; i += THREADS) {     // x tile
        const int c = i >> 7, pix = i & 127;
        const int r = pix >> 5, col = pix & 31;
        x_s[c * X_PITCH + pix] =
            x[(((size_t)b * C_IN + c) * H_SZ + (h0 + r)) * W_SZ + (w0 + col)];
    }
    if (tid < HID)  b1_s[tid] = b1[tid];
    if (tid < C_IN) b2_s[tid] = b2[tid];
    __syncthreads();

    // ---- persistent GEMM2 accumulators (f32x2 pairs): 4 c x 4 pairs ----
    ull acc2[4][4];
    #pragma unroll
    for (int i = 0; i < 4; ++i) {
        const ull init = (khalf == 0) ? pack2(b2_s[crow + i]) : 0ULL;
        #pragma unroll
        for (int j = 0; j < 4; ++j) acc2[i][j] = init;
    }

    #pragma unroll 1
    for (int ch = 0; ch < 2; ++ch) {
        const int hidbase = ch * CH_HID;

        // ================= GEMM1: 16 hid x 64 pix per warp, K=64 =========
        ull acc1[4][4];
        #pragma unroll
        for (int i = 0; i < 4; ++i)
            #pragma unroll
            for (int j = 0; j < 4; ++j) acc1[i][j] = 0ULL;

        {
            const float* wp = w1_s + hidbase + wrow;
            const float* xp = x_s + pixb;
            #pragma unroll 8
            for (int k = 0; k < 64; ++k) {
                const float4 wv = *(const float4*)(wp + k * W1_PITCH);
                const ull wpk0 = pack2(wv.x);
                const ull wpk1 = pack2(wv.y);
                const ull wpk2 = pack2(wv.z);
                const ull wpk3 = pack2(wv.w);
                const ulonglong2 xa = *(const ulonglong2*)(xp + k * X_PITCH);
                const ulonglong2 xb = *(const ulonglong2*)(xp + k * X_PITCH + 4);
                acc1[0][0] = fma2(wpk0, xa.x, acc1[0][0]);
                acc1[0][1] = fma2(wpk0, xa.y, acc1[0][1]);
                acc1[0][2] = fma2(wpk0, xb.x, acc1[0][2]);
                acc1[0][3] = fma2(wpk0, xb.y, acc1[0][3]);
                acc1[1][0] = fma2(wpk1, xa.x, acc1[1][0]);
                acc1[1][1] = fma2(wpk1, xa.y, acc1[1][1]);
                acc1[1][2] = fma2(wpk1, xb.x, acc1[1][2]);
                acc1[1][3] = fma2(wpk1, xb.y, acc1[1][3]);
                acc1[2][0] = fma2(wpk2, xa.x, acc1[2][0]);
                acc1[2][1] = fma2(wpk2, xa.y, acc1[2][1]);
                acc1[2][2] = fma2(wpk2, xb.x, acc1[2][2]);
                acc1[2][3] = fma2(wpk2, xb.y, acc1[2][3]);
                acc1[3][0] = fma2(wpk3, xa.x, acc1[3][0]);
                acc1[3][1] = fma2(wpk3, xa.y, acc1[3][1]);
                acc1[3][2] = fma2(wpk3, xb.x, acc1[3][2]);
                acc1[3][3] = fma2(wpk3, xb.y, acc1[3][3]);
            }
        }

        __syncthreads();   // h_s + w2c_s free (prev GEMM2 done reading)

        // ---- store FULL w2 chunk (from prefetched regs), prefetch next ----
        #pragma unroll
        for (int j = 0; j < 4; ++j) {
            const int hh = h4 + j * 32;
            w2c_s[(hh + 0) * W2C_PITCH + c_w2] = pw2[j].x;
            w2c_s[(hh + 1) * W2C_PITCH + c_w2] = pw2[j].y;
            w2c_s[(hh + 2) * W2C_PITCH + c_w2] = pw2[j].z;
            w2c_s[(hh + 3) * W2C_PITCH + c_w2] = pw2[j].w;
        }
        if (ch == 0) {
            #pragma unroll
            for (int j = 0; j < 4; ++j)
                pw2[j] = *(const float4*)&w2[c_w2 * 256 + CH_HID + h4 + j * 32];
        }

        // ---- bias + exact GELU, store h tile ----
        #pragma unroll
        for (int hh = 0; hh < 4; ++hh) {
            const float bb = b1_s[hidbase + wrow + hh];
            float v[8];
            unpack2(acc1[hh][0], v[0], v[1]);
            unpack2(acc1[hh][1], v[2], v[3]);
            unpack2(acc1[hh][2], v[4], v[5]);
            unpack2(acc1[hh][3], v[6], v[7]);
            float4 g0, g1;
            g0.x = gelu_exact(v[0] + bb); g0.y = gelu_exact(v[1] + bb);
            g0.z = gelu_exact(v[2] + bb); g0.w = gelu_exact(v[3] + bb);
            g1.x = gelu_exact(v[4] + bb); g1.y = gelu_exact(v[5] + bb);
            g1.z = gelu_exact(v[6] + bb); g1.w = gelu_exact(v[7] + bb);
            *(float4*)&h_s[(wrow + hh) * H_PITCH + pixb]     = g0;
            *(float4*)&h_s[(wrow + hh) * H_PITCH + pixb + 4] = g1;
        }
        __syncthreads();

        // ================= GEMM2: 16 c x 64 pix per warp-pair, K split ====
        {
            const float* wp2 = w2c_s + khalf * 64 * W2C_PITCH + crow;
            const float* hp  = h_s + khalf * 64 * H_PITCH + pixb2;
            #pragma unroll 8
            for (int k = 0; k < 64; ++k) {
                const float4 wv = *(const float4*)(wp2 + k * W2C_PITCH);
                const ull wpk0 = pack2(wv.x);
                const ull wpk1 = pack2(wv.y);
                const ull wpk2 = pack2(wv.z);
                const ull wpk3 = pack2(wv.w);
                const ulonglong2 ha = *(const ulonglong2*)(hp + k * H_PITCH);
                const ulonglong2 hb = *(const ulonglong2*)(hp + k * H_PITCH + 4);
                acc2[0][0] = fma2(wpk0, ha.x, acc2[0][0]);
                acc2[0][1] = fma2(wpk0, ha.y, acc2[0][1]);
                acc2[0][2] = fma2(wpk0, hb.x, acc2[0][2]);
                acc2[0][3] = fma2(wpk0, hb.y, acc2[0][3]);
                acc2[1][0] = fma2(wpk1, ha.x, acc2[1][0]);
                acc2[1][1] = fma2(wpk1, ha.y, acc2[1][1]);
                acc2[1][2] = fma2(wpk1, hb.x, acc2[1][2]);
                acc2[1][3] = fma2(wpk1, hb.y, acc2[1][3]);
                acc2[2][0] = fma2(wpk2, ha.x, acc2[2][0]);
                acc2[2][1] = fma2(wpk2, ha.y, acc2[2][1]);
                acc2[2][2] = fma2(wpk2, hb.x, acc2[2][2]);
                acc2[2][3] = fma2(wpk2, hb.y, acc2[2][3]);
                acc2[3][0] = fma2(wpk3, ha.x, acc2[3][0]);
                acc2[3][1] = fma2(wpk3, ha.y, acc2[3][1]);
                acc2[3][2] = fma2(wpk3, hb.x, acc2[3][2]);
                acc2[3][3] = fma2(wpk3, hb.y, acc2[3][3]);
            }
        }
    }

    __syncthreads();   // x_s, h_s, w2c_s all free now

    // ---- combine GEMM2 k-halves in y_s ( = x_s region ), copy mix mats ----
    float* y_s = x_s;                       // [64][X_PITCH]
    float* m_s = h_s;                       // 64KB overlay in h region

    if (khalf == 0) {
        #pragma unroll
        for (int i = 0; i < 4; ++i) {
            float v[8];
            unpack2(acc2[i][0], v[0], v[1]);
            unpack2(acc2[i][1], v[2], v[3]);
            unpack2(acc2[i][2], v[4], v[5]);
            unpack2(acc2[i][3], v[6], v[7]);
            *(float4*)&y_s[(crow + i) * X_PITCH + pixb2]     = make_float4(v[0], v[1], v[2], v[3]);
            *(float4*)&y_s[(crow + i) * X_PITCH + pixb2 + 4] = make_float4(v[4], v[5], v[6], v[7]);
        }
    }
    for (int i = tid; i < 64 * 256; i += THREADS) m_s[i] = g_M[i];
    __syncthreads();

    if (khalf == 1) {
        #pragma unroll
        for (int i = 0; i < 4; ++i) {
            ull* p0 = (ull*)&y_s[(crow + i) * X_PITCH + pixb2];
            p0[0] = add2(p0[0], acc2[i][0]);
            p0[1] = add2(p0[1], acc2[i][1]);
            p0[2] = add2(p0[2], acc2[i][2]);
            p0[3] = add2(p0[3], acc2[i][3]);
        }
    }
    __syncthreads();

    // ---- Fourier mix: one 4x4 window per thread ----
    const int c  = tid >> 3;   // channel 0..63
    const int wc = tid & 7;    // window col 0..7

    float pin[16];
    #pragma unroll
    for (int r = 0; r < 4; ++r) {
        const float4 v = *(const float4*)&y_s[c * X_PITCH + r * 32 + wc * 4];
        pin[r * 4 + 0] = v.x; pin[r * 4 + 1] = v.y;
        pin[r * 4 + 2] = v.z; pin[r * 4 + 3] = v.w;
    }

    float po[16];
    const float* mrow = &m_s[c * 256];
    #pragma unroll
    for (int o = 0; o < 16; ++o) {
        float s = 0.f;
        #pragma unroll
        for (int i4 = 0; i4 < 4; ++i4) {
            const float4 mv = *(const float4*)&mrow[o * 16 + i4 * 4];
            s += mv.x * pin[i4 * 4 + 0];
            s += mv.y * pin[i4 * 4 + 1];
            s += mv.z * pin[i4 * 4 + 2];
            s += mv.w * pin[i4 * 4 + 3];
        }
        po[o] = s;
    }

    const size_t obase = (((size_t)b * C_IN + c) * H_SZ + h0) * W_SZ + w0 + wc * 4;
    #pragma unroll
    for (int r = 0; r < 4; ++r) {
        float4 v;
        v.x = po[r * 4 + 0]; v.y = po[r * 4 + 1];
        v.z = po[r * 4 + 2]; v.w = po[r * 4 + 3];
        *(float4*)&out[obase + (size_t)r * W_SZ] = v;
    }
}

// ---------------------------------------------------------------------------
// Launch
// ---------------------------------------------------------------------------
extern "C" void kernel_launch(void* const* d_in, const int* in_sizes, int n_in,
                              void* d_out, int out_size) {
    const float* x  = (const float*)d_in[0];
    const float* w1 = (const float*)d_in[1];
    const float* b1 = (const float*)d_in[2];
    const float* w2 = (const float*)d_in[3];
    const float* b2 = (const float*)d_in[4];
    const float* cw = (const float*)d_in[5];
    float* out = (float*)d_out;

    cudaFuncSetAttribute(fmffn_kernel,
                         cudaFuncAttributeMaxDynamicSharedMemorySize, SMEM_BYTES);

    build_mix_kernel<<<64, 256>>>(cw);

    dim3 grid(W_SZ / TCOLS, H_SZ / TROWS, B_SZ);  // (8, 64, 8)
    fmffn_kernel<<<grid, THREADS, SMEM_BYTES>>>(x, w1, b1, w2, b2, out);
}

// round 7
// speedup vs baseline: 1.8380x; 1.8380x over previous
#include <cuda_runtime.h>
#include <cuda_bf16.h>
#include <math.h>
#include <stdint.h>

#define B_SZ   8
#define C_IN   64
#define HID    256
#define H_SZ   256
#define W_SZ   256
#define THREADS 512

// bf16 tiles pitch: 72 halfs = 144 B (9 x 16B -> ldmatrix conflict-free)
#define PITCH    72
#define PITCHB   144
#define W2PITCH  264          // halfs (528 B = 33 x 16B)
#define W2PITCHB 528

// ---------------- smem layout (bytes) ----------------
#define XH_OFF   0            // 128 x 72 bf16 = 18432
#define XL_OFF   18432
#define W1H_OFF  36864        // 256 x 72 bf16 = 36864
#define W1L_OFF  73728
#define W2H_OFF  110592       // 64 x 264 bf16 = 33792
#define W2L_OFF  144384
#define HH_OFF   178176       // 128 x 72 bf16 = 18432
#define HL_OFF   196608
#define B1S_OFF  215040       // 256 f32
#define B2S_OFF  216064       // 64 f32
#define SMEM_BYTES 216320

// overlays for final stage
#define YS_OFF  W1H_OFF       // 64 x 132 f32 = 33792 (< 36864)
#define MS_OFF  W2H_OFF       // 64KB mix matrices (< 67584)
#define X_PITCH 132

// ---------------------------------------------------------------------------
__device__ __forceinline__ uint32_t smem_u32(const void* p) {
    uint32_t a;
    asm("{ .reg .u64 t; cvta.to.shared.u64 t, %1; cvt.u32.u64 %0, t; }" : "=r"(a) : "l"(p));
    return a;
}

#define LDSM4(r0, r1, r2, r3, addr) \
    asm volatile("ldmatrix.sync.aligned.m8n8.x4.shared.b16 {%0,%1,%2,%3}, [%4];" \
        : "=r"(r0), "=r"(r1), "=r"(r2), "=r"(r3) : "r"(addr))

__device__ __forceinline__ void mma16816(float* d, const uint32_t* a, const uint32_t* b) {
    asm volatile(
        "mma.sync.aligned.m16n8k16.row.col.f32.bf16.bf16.f32 "
        "{%0,%1,%2,%3}, {%4,%5,%6,%7}, {%8,%9}, {%0,%1,%2,%3};"
        : "+f"(d[0]), "+f"(d[1]), "+f"(d[2]), "+f"(d[3])
        : "r"(a[0]), "r"(a[1]), "r"(a[2]), "r"(a[3]), "r"(b[0]), "r"(b[1]));
}

__device__ __forceinline__ uint32_t pbf2(__nv_bfloat16 a, __nv_bfloat16 b) {
    uint32_t r;
    asm("mov.b32 %0, {%1, %2};" : "=r"(r)
        : "h"(__bfloat16_as_ushort(a)), "h"(__bfloat16_as_ushort(b)));
    return r;
}

__device__ __forceinline__ float gelu_exact(float x) {
    return 0.5f * x * (1.f + erff(x * 0.70710678118654752440f));
}

// ---------------------------------------------------------------------------
// Per-channel 16x16 Fourier-mix matrix (P=4, exact twiddles)
// ---------------------------------------------------------------------------
__device__ float g_M[64 * 256];

__global__ void build_mix_kernel(const float* __restrict__ cw) {
    const int c   = blockIdx.x;
    const int t   = threadIdx.x;
    const int in  = t >> 4;
    const int out = t & 15;
    const int s  = in >> 2, tt = in & 3;
    const int p  = out >> 2, q  = out & 3;
    const float cs[4] = {1.f, 0.f, -1.f, 0.f};
    const float sn[4] = {0.f, 1.f, 0.f, -1.f};
    float tre[3] = {0.f, 0.f, 0.f};
    float tim[3] = {0.f, 0.f, 0.f};
    #pragma unroll
    for (int u = 0; u < 4; ++u) {
        const int e2 = (u * p) & 3;
        const float c2 = cs[e2], s2 = sn[e2];
        #pragma unroll
        for (int v = 0; v < 3; ++v) {
            const int e1 = (4 - ((u * s + v * tt) & 3)) & 3;
            const float yr = 0.25f * cs[e1];
            const float yi = 0.25f * sn[e1];
            const float wr = cw[((u * 3 + v) * 64 + c) * 2 + 0];
            const float wi = cw[((u * 3 + v) * 64 + c) * 2 + 1];
            const float zr = yr * wr - yi * wi;
            const float zi = yr * wi + yi * wr;
            tre[v] += zr * c2 - zi * s2;
            tim[v] += zr * s2 + zi * c2;
        }
    }
    const float sgn = (q & 1) ? -1.f : 1.f;
    g_M[c * 256 + out * 16 + in] =
        0.25f * (tre[0] + sgn * tre[2] + 2.f * (tre[1] * cs[q] - tim[1] * sn[q]));
}

// ---------------------------------------------------------------------------
// Main kernel: mma.sync bf16-split FFN + Fourier window mix
// ---------------------------------------------------------------------------
__global__ __launch_bounds__(THREADS, 1)
void fmffn_kernel(const float* __restrict__ x,
                  const float* __restrict__ w1,
                  const float* __restrict__ b1,
                  const float* __restrict__ w2,
                  const float* __restrict__ b2,
                  float* __restrict__ out) {
    extern __shared__ char smem[];
    const uint32_t sb = smem_u32(smem);

    const int tid  = threadIdx.x;
    const int wid  = tid >> 5;
    const int lane = tid & 31;
    const int b    = blockIdx.z;
    const int h0   = blockIdx.y * 4;
    const int w0   = blockIdx.x * 32;

    float* b1_s = (float*)(smem + B1S_OFF);
    float* b2_s = (float*)(smem + B2S_OFF);

    // ---- staging: fp32 -> bf16 hi/lo ----
    for (int i = tid; i < 64 * 128; i += THREADS) {            // x: [pix][c]
        const int c = i >> 7, pix = i & 127;
        const int r = pix >> 5, col = pix & 31;
        const float v = x[(((size_t)b * C_IN + c) * H_SZ + (h0 + r)) * W_SZ + (w0 + col)];
        const __nv_bfloat16 hi = __float2bfloat16(v);
        const __nv_bfloat16 lo = __float2bfloat16(v - __bfloat162float(hi));
        const uint32_t o = pix * PITCHB + c * 2;
        *(__nv_bfloat16*)(smem + XH_OFF + o) = hi;
        *(__nv_bfloat16*)(smem + XL_OFF + o) = lo;
    }
    for (int i = tid; i < HID * C_IN; i += THREADS) {          // w1: [hid][c]
        const int hid = i >> 6, c = i & 63;
        const float v = w1[i];
        const __nv_bfloat16 hi = __float2bfloat16(v);
        const __nv_bfloat16 lo = __float2bfloat16(v - __bfloat162float(hi));
        const uint32_t o = hid * PITCHB + c * 2;
        *(__nv_bfloat16*)(smem + W1H_OFF + o) = hi;
        *(__nv_bfloat16*)(smem + W1L_OFF + o) = lo;
    }
    for (int i = tid; i < C_IN * HID; i += THREADS) {          // w2: [c][hid]
        const int c = i >> 8, hid = i & 255;
        const float v = w2[i];
        const __nv_bfloat16 hi = __float2bfloat16(v);
        const __nv_bfloat16 lo = __float2bfloat16(v - __bfloat162float(hi));
        const uint32_t o = c * W2PITCHB + hid * 2;
        *(__nv_bfloat16*)(smem + W2H_OFF + o) = hi;
        *(__nv_bfloat16*)(smem + W2L_OFF + o) = lo;
    }
    if (tid < HID)  b1_s[tid] = b1[tid];
    if (tid < C_IN) b2_s[tid] = b2[tid];
    __syncthreads();

    // ---- warp geometry ----
    const int wr  = wid & 3;              // pixel row group (32 pix)
    const int wcg = wid >> 2;             // n col group (16)
    const int aRow = (lane & 7) + ((lane >> 3) & 1) * 8;   // A frag row-in-tile
    const int aKof = (lane >> 4) * 8;                       // A frag k offset
    const int bRow = (lane & 7) + (lane >> 4) * 8;          // B frag row-in-tile
    const int bKof = ((lane >> 3) & 1) * 8;                 // B frag k offset

    // lane's element coords within an mma tile (D layout)
    const int dRow = lane >> 2;           // + 8 for regs 2,3
    const int dCol = (lane & 3) * 2;

    // precomputed ldmatrix base addresses
    const uint32_t aXbase = sb + (uint32_t)((wr * 32 + aRow) * PITCHB + aKof * 2);
    const uint32_t bW1base = sb + W1H_OFF + (uint32_t)((wcg * 16 + bRow) * PITCHB + bKof * 2);
    const uint32_t bW2base = sb + W2H_OFF + (uint32_t)((wcg * 16 + bRow) * W2PITCHB + bKof * 2);
    const uint32_t aHbase = sb + HH_OFF + (uint32_t)((wr * 32 + aRow) * PITCHB + aKof * 2);
#define W1LD (W1L_OFF - W1H_OFF)
#define W2LD (W2L_OFF - W2H_OFF)

    // persistent GEMM2 accumulators: tiles [mt][nt], 4 regs each
    float acc2[2][2][4];
    #pragma unroll
    for (int mt = 0; mt < 2; ++mt)
        #pragma unroll
        for (int nt = 0; nt < 2; ++nt)
            #pragma unroll
            for (int j = 0; j < 4; ++j) acc2[mt][nt][j] = 0.f;

    // ---- 4 hid chunks of 64 ----
    #pragma unroll 1
    for (int nc = 0; nc < 4; ++nc) {

        // ===== GEMM1 chunk: C1[128 pix x 64 hid], K = 64 (c) =====
        float acc1[2][2][4];
        #pragma unroll
        for (int mt = 0; mt < 2; ++mt)
            #pragma unroll
            for (int nt = 0; nt < 2; ++nt)
                #pragma unroll
                for (int j = 0; j < 4; ++j) acc1[mt][nt][j] = 0.f;

        #pragma unroll
        for (int ks = 0; ks < 4; ++ks) {
            uint32_t axh[8], axl[8], bh[4], bl[4];
            LDSM4(axh[0], axh[1], axh[2], axh[3], aXbase + XH_OFF + ks * 32);
            LDSM4(axh[4], axh[5], axh[6], axh[7], aXbase + XH_OFF + 16 * PITCHB + ks * 32);
            LDSM4(axl[0], axl[1], axl[2], axl[3], aXbase + XL_OFF + ks * 32);
            LDSM4(axl[4], axl[5], axl[6], axl[7], aXbase + XL_OFF + 16 * PITCHB + ks * 32);
            LDSM4(bh[0], bh[1], bh[2], bh[3], bW1base + nc * 64 * PITCHB + ks * 32);
            LDSM4(bl[0], bl[1], bl[2], bl[3], bW1base + W1LD + nc * 64 * PITCHB + ks * 32);
            #pragma unroll
            for (int mt = 0; mt < 2; ++mt)
                #pragma unroll
                for (int nt = 0; nt < 2; ++nt) {
                    mma16816(acc1[mt][nt], axh + mt * 4, bh + nt * 2);
                    mma16816(acc1[mt][nt], axh + mt * 4, bl + nt * 2);
                    mma16816(acc1[mt][nt], axl + mt * 4, bh + nt * 2);
                }
        }

        __syncthreads();   // previous chunk's GEMM2 reads of H done

        // ---- bias + exact GELU -> bf16 hi/lo -> H smem ----
        #pragma unroll
        for (int mt = 0; mt < 2; ++mt)
            #pragma unroll
            for (int nt = 0; nt < 2; ++nt) {
                const int nl = wcg * 16 + nt * 8 + dCol;           // 0..63
                const float bb0 = b1_s[nc * 64 + nl];
                const float bb1 = b1_s[nc * 64 + nl + 1];
                const int r0 = wr * 32 + mt * 16 + dRow;
                #pragma unroll
                for (int hh = 0; hh < 2; ++hh) {
                    const float g0 = gelu_exact(acc1[mt][nt][hh * 2 + 0] + bb0);
                    const float g1 = gelu_exact(acc1[mt][nt][hh * 2 + 1] + bb1);
                    const __nv_bfloat16 h0 = __float2bfloat16(g0);
                    const __nv_bfloat16 h1 = __float2bfloat16(g1);
                    const uint32_t o = (uint32_t)((r0 + hh * 8) * PITCHB + nl * 2);
                    *(uint32_t*)(smem + HH_OFF + o) = pbf2(h0, h1);
                    *(uint32_t*)(smem + HL_OFF + o) =
                        pbf2(__float2bfloat16(g0 - __bfloat162float(h0)),
                             __float2bfloat16(g1 - __bfloat162float(h1)));
                }
            }
        __syncthreads();

        // ===== GEMM2 accumulate: C2[128 pix x 64 c] += H * W2^T, K = 64 =====
        #pragma unroll
        for (int ks = 0; ks < 4; ++ks) {
            uint32_t ahh[8], ahl[8], bh[4], bl[4];
            LDSM4(ahh[0], ahh[1], ahh[2], ahh[3], aHbase + ks * 32);
            LDSM4(ahh[4], ahh[5], ahh[6], ahh[7], aHbase + 16 * PITCHB + ks * 32);
            LDSM4(ahl[0], ahl[1], ahl[2], ahl[3], aHbase + (HL_OFF - HH_OFF) + ks * 32);
            LDSM4(ahl[4], ahl[5], ahl[6], ahl[7],
                  aHbase + (HL_OFF - HH_OFF) + 16 * PITCHB + ks * 32);
            LDSM4(bh[0], bh[1], bh[2], bh[3], bW2base + nc * 128 + ks * 32);
            LDSM4(bl[0], bl[1], bl[2], bl[3], bW2base + W2LD + nc * 128 + ks * 32);
            #pragma unroll
            for (int mt = 0; mt < 2; ++mt)
                #pragma unroll
                for (int nt = 0; nt < 2; ++nt) {
                    mma16816(acc2[mt][nt], ahh + mt * 4, bh + nt * 2);
                    mma16816(acc2[mt][nt], ahh + mt * 4, bl + nt * 2);
                    mma16816(acc2[mt][nt], ahl + mt * 4, bh + nt * 2);
                }
        }
    }

    __syncthreads();   // W1/W2/X regions free for overlays

    // ---- write y (+bias) to y_s; copy mix matrices ----
    float* y_s = (float*)(smem + YS_OFF);    // [64][132]
    float* m_s = (float*)(smem + MS_OFF);

    #pragma unroll
    for (int mt = 0; mt < 2; ++mt)
        #pragma unroll
        for (int nt = 0; nt < 2; ++nt) {
            const int c0 = wcg * 16 + nt * 8 + dCol;
            const int r0 = wr * 32 + mt * 16 + dRow;
            #pragma unroll
            for (int hh = 0; hh < 2; ++hh) {
                y_s[(c0)     * X_PITCH + r0 + hh * 8] = acc2[mt][nt][hh * 2 + 0] + b2_s[c0];
                y_s[(c0 + 1) * X_PITCH + r0 + hh * 8] = acc2[mt][nt][hh * 2 + 1] + b2_s[c0 + 1];
            }
        }
    for (int i = tid; i < 64 * 256; i += THREADS) m_s[i] = g_M[i];
    __syncthreads();

    // ---- Fourier mix: one 4x4 window per thread ----
    const int c  = tid >> 3;
    const int wc = tid & 7;

    float pin[16];
    #pragma unroll
    for (int r4 = 0; r4 < 4; ++r4) {
        const float4 v = *(const float4*)&y_s[c * X_PITCH + r4 * 32 + wc * 4];
        pin[r4 * 4 + 0] = v.x; pin[r4 * 4 + 1] = v.y;
        pin[r4 * 4 + 2] = v.z; pin[r4 * 4 + 3] = v.w;
    }

    float po[16];
    const float* mrow = &m_s[c * 256];
    #pragma unroll
    for (int o = 0; o < 16; ++o) {
        float s = 0.f;
        #pragma unroll
        for (int i4 = 0; i4 < 4; ++i4) {
            const float4 mv = *(const float4*)&mrow[o * 16 + i4 * 4];
            s += mv.x * pin[i4 * 4 + 0];
            s += mv.y * pin[i4 * 4 + 1];
            s += mv.z * pin[i4 * 4 + 2];
            s += mv.w * pin[i4 * 4 + 3];
        }
        po[o] = s;
    }

    const size_t obase = (((size_t)b * C_IN + c) * H_SZ + h0) * W_SZ + w0 + wc * 4;
    #pragma unroll
    for (int r4 = 0; r4 < 4; ++r4) {
        *(float4*)&out[obase + (size_t)r4 * W_SZ] =
            make_float4(po[r4 * 4 + 0], po[r4 * 4 + 1], po[r4 * 4 + 2], po[r4 * 4 + 3]);
    }
}

// ---------------------------------------------------------------------------
extern "C" void kernel_launch(void* const* d_in, const int* in_sizes, int n_in,
                              void* d_out, int out_size) {
    const float* x  = (const float*)d_in[0];
    const float* w1 = (const float*)d_in[1];
    const float* b1 = (const float*)d_in[2];
    const float* w2 = (const float*)d_in[3];
    const float* b2 = (const float*)d_in[4];
    const float* cw = (const float*)d_in[5];
    float* out = (float*)d_out;

    cudaFuncSetAttribute(fmffn_kernel,
                         cudaFuncAttributeMaxDynamicSharedMemorySize, SMEM_BYTES);

    build_mix_kernel<<<64, 256>>>(cw);

    dim3 grid(W_SZ / 32, H_SZ / 4, B_SZ);   // (8, 64, 8)
    fmffn_kernel<<<grid, THREADS, SMEM_BYTES>>>(x, w1, b1, w2, b2, out);
}

// round 8
// speedup vs baseline: 3.3724x; 1.8348x over previous
#include <cuda_runtime.h>
#include <cuda_bf16.h>
#include <math.h>
#include <stdint.h>

#define B_SZ   8
#define C_IN   64
#define HID    256
#define H_SZ   256
#define W_SZ   256
#define THREADS 256

// all bf16 tiles: 64 cols x 2B = 128 B data + 16 pad = 144 B pitch (9x16B)
#define PITCHB 144

// ---------------- smem layout (bytes) ----------------
#define XH_OFF   0            // 128 x 144 = 18432
#define XL_OFF   18432
#define HH_OFF   36864
#define HL_OFF   55296
#define W1CH_OFF 73728        // 64 x 144 = 9216
#define W1CL_OFF 82944
#define W2CH_OFF 92160
#define W2CL_OFF 101376
#define B1S_OFF  110592       // 256 f32
#define B2S_OFF  111616       // 64 f32
#define SMEM_BYTES 111872

// overlays for final stage
#define YS_OFF  0             // 64 x 132 f32 = 33792 over X region
#define MS_OFF  36864         // 65536 over H + W1c + W2c regions
#define X_PITCH 132

// ---------------------------------------------------------------------------
__device__ __forceinline__ uint32_t smem_u32(const void* p) {
    uint32_t a;
    asm("{ .reg .u64 t; cvta.to.shared.u64 t, %1; cvt.u32.u64 %0, t; }" : "=r"(a) : "l"(p));
    return a;
}

#define LDSM4(r0, r1, r2, r3, addr) \
    asm volatile("ldmatrix.sync.aligned.m8n8.x4.shared.b16 {%0,%1,%2,%3}, [%4];" \
        : "=r"(r0), "=r"(r1), "=r"(r2), "=r"(r3) : "r"(addr))

__device__ __forceinline__ void mma16816(float* d, const uint32_t* a, const uint32_t* b) {
    asm volatile(
        "mma.sync.aligned.m16n8k16.row.col.f32.bf16.bf16.f32 "
        "{%0,%1,%2,%3}, {%4,%5,%6,%7}, {%8,%9}, {%0,%1,%2,%3};"
        : "+f"(d[0]), "+f"(d[1]), "+f"(d[2]), "+f"(d[3])
        : "r"(a[0]), "r"(a[1]), "r"(a[2]), "r"(a[3]), "r"(b[0]), "r"(b[1]));
}

__device__ __forceinline__ void cp16(uint32_t dst, const void* src) {
    asm volatile("cp.async.cg.shared.global [%0], [%1], 16;"
                 :: "r"(dst), "l"(__cvta_generic_to_global(src)) : "memory");
}
__device__ __forceinline__ void cp_commit() {
    asm volatile("cp.async.commit_group;" ::: "memory");
}
template <int N>
__device__ __forceinline__ void cp_wait() {
    asm volatile("cp.async.wait_group %0;" :: "n"(N) : "memory");
}

__device__ __forceinline__ uint32_t pbf2(__nv_bfloat16 a, __nv_bfloat16 b) {
    uint32_t r;
    asm("mov.b32 %0, {%1, %2};" : "=r"(r)
        : "h"(__bfloat16_as_ushort(a)), "h"(__bfloat16_as_ushort(b)));
    return r;
}

__device__ __forceinline__ float gelu_exact(float x) {
    return 0.5f * x * (1.f + erff(x * 0.70710678118654752440f));
}

// ---------------------------------------------------------------------------
// Precomputed global scratch: mix matrices + bf16 hi/lo weight splits
// ---------------------------------------------------------------------------
__device__ float g_M[64 * 256];
__device__ __nv_bfloat16 g_w1h[HID * C_IN], g_w1l[HID * C_IN];
__device__ __nv_bfloat16 g_w2h[C_IN * HID], g_w2l[C_IN * HID];

__global__ void build_mix_kernel(const float* __restrict__ cw) {
    const int c   = blockIdx.x;
    const int t   = threadIdx.x;
    const int in  = t >> 4;
    const int out = t & 15;
    const int s  = in >> 2, tt = in & 3;
    const int p  = out >> 2, q  = out & 3;
    const float cs[4] = {1.f, 0.f, -1.f, 0.f};
    const float sn[4] = {0.f, 1.f, 0.f, -1.f};
    float tre[3] = {0.f, 0.f, 0.f};
    float tim[3] = {0.f, 0.f, 0.f};
    #pragma unroll
    for (int u = 0; u < 4; ++u) {
        const int e2 = (u * p) & 3;
        const float c2 = cs[e2], s2 = sn[e2];
        #pragma unroll
        for (int v = 0; v < 3; ++v) {
            const int e1 = (4 - ((u * s + v * tt) & 3)) & 3;
            const float yr = 0.25f * cs[e1];
            const float yi = 0.25f * sn[e1];
            const float wr = cw[((u * 3 + v) * 64 + c) * 2 + 0];
            const float wi = cw[((u * 3 + v) * 64 + c) * 2 + 1];
            const float zr = yr * wr - yi * wi;
            const float zi = yr * wi + yi * wr;
            tre[v] += zr * c2 - zi * s2;
            tim[v] += zr * s2 + zi * c2;
        }
    }
    const float sgn = (q & 1) ? -1.f : 1.f;
    g_M[c * 256 + out * 16 + in] =
        0.25f * (tre[0] + sgn * tre[2] + 2.f * (tre[1] * cs[q] - tim[1] * sn[q]));
}

__global__ void build_weights_kernel(const float* __restrict__ w1,
                                     const float* __restrict__ w2) {
    const int i = blockIdx.x * blockDim.x + threadIdx.x;   // 0..32767
    if (i < HID * C_IN) {
        const float v = w1[i];
        const __nv_bfloat16 hi = __float2bfloat16(v);
        g_w1h[i] = hi;
        g_w1l[i] = __float2bfloat16(v - __bfloat162float(hi));
    } else {
        const int j = i - HID * C_IN;
        const float v = w2[j];
        const __nv_bfloat16 hi = __float2bfloat16(v);
        g_w2h[j] = hi;
        g_w2l[j] = __float2bfloat16(v - __bfloat162float(hi));
    }
}

// ---------------------------------------------------------------------------
// Main kernel
// ---------------------------------------------------------------------------
__global__ __launch_bounds__(THREADS, 2)
void fmffn_kernel(const float* __restrict__ x,
                  const float* __restrict__ b1,
                  const float* __restrict__ b2,
                  float* __restrict__ out) {
    extern __shared__ char smem[];
    const uint32_t sb = smem_u32(smem);

    const int tid  = threadIdx.x;
    const int wid  = tid >> 5;
    const int lane = tid & 31;
    const int b    = blockIdx.z;
    const int h0   = blockIdx.y * 4;
    const int w0   = blockIdx.x * 32;

    float* b1_s = (float*)(smem + B1S_OFF);
    float* b2_s = (float*)(smem + B2S_OFF);

    // ---- issue weight chunk 0 copies (W1 group, then W2 group) ----
    {
        for (int i = tid; i < 512; i += THREADS) {   // 64 rows x 8 segs
            const int row = i >> 3, seg = i & 7;
            cp16(sb + W1CH_OFF + row * PITCHB + seg * 16,
                 (const char*)g_w1h + row * 128 + seg * 16);
            cp16(sb + W1CL_OFF + row * PITCHB + seg * 16,
                 (const char*)g_w1l + row * 128 + seg * 16);
        }
        cp_commit();
        for (int i = tid; i < 512; i += THREADS) {
            const int row = i >> 3, seg = i & 7;     // row = c
            cp16(sb + W2CH_OFF + row * PITCHB + seg * 16,
                 (const char*)g_w2h + row * 512 + seg * 16);
            cp16(sb + W2CL_OFF + row * PITCHB + seg * 16,
                 (const char*)g_w2l + row * 512 + seg * 16);
        }
        cp_commit();
    }

    // ---- stage x -> bf16 hi/lo [pix][c] ----
    for (int i = tid; i < 64 * 128; i += THREADS) {
        const int c = i >> 7, pix = i & 127;
        const int r = pix >> 5, col = pix & 31;
        const float v = x[(((size_t)b * C_IN + c) * H_SZ + (h0 + r)) * W_SZ + (w0 + col)];
        const __nv_bfloat16 hi = __float2bfloat16(v);
        const __nv_bfloat16 lo = __float2bfloat16(v - __bfloat162float(hi));
        const uint32_t o = pix * PITCHB + c * 2;
        *(__nv_bfloat16*)(smem + XH_OFF + o) = hi;
        *(__nv_bfloat16*)(smem + XL_OFF + o) = lo;
    }
    if (tid < HID)  b1_s[tid] = b1[tid];
    if (tid < C_IN) b2_s[tid] = b2[tid];

    // ---- warp geometry: 8 warps = 4 pixel groups x 2 n groups ----
    const int pr  = wid & 3;              // pixel group (32 pix)
    const int wcg = wid >> 2;             // n group (32 n)
    const int aRow = (lane & 7) + ((lane >> 3) & 1) * 8;
    const int aKof = (lane >> 4) * 8;
    const int bRow = (lane & 7) + (lane >> 4) * 8;
    const int bKof = ((lane >> 3) & 1) * 8;
    const int dRow = lane >> 2;
    const int dCol = (lane & 3) * 2;

    const uint32_t aXbase  = sb + XH_OFF + (uint32_t)((pr * 32 + aRow) * PITCHB + aKof * 2);
    const uint32_t aHbase  = sb + HH_OFF + (uint32_t)((pr * 32 + aRow) * PITCHB + aKof * 2);
    const uint32_t bW1base = sb + W1CH_OFF + (uint32_t)((wcg * 32 + bRow) * PITCHB + bKof * 2);
    const uint32_t bW2base = sb + W2CH_OFF + (uint32_t)((wcg * 32 + bRow) * PITCHB + bKof * 2);
#define XLD   (XL_OFF - XH_OFF)
#define HLD   (HL_OFF - HH_OFF)
#define W1LD  (W1CL_OFF - W1CH_OFF)
#define W2LD  (W2CL_OFF - W2CH_OFF)

    // persistent GEMM2 accumulators: [mt2][nt4][4]
    float acc2[2][4][4];
    #pragma unroll
    for (int mt = 0; mt < 2; ++mt)
        #pragma unroll
        for (int nt = 0; nt < 4; ++nt)
            #pragma unroll
            for (int j = 0; j < 4; ++j) acc2[mt][nt][j] = 0.f;

    // ---- 4 hid chunks of 64 ----
    #pragma unroll 1
    for (int nc = 0; nc < 4; ++nc) {
        // W1(nc) (and at nc=0 also W2(0)) must be complete
        cp_wait<0>();
        __syncthreads();                               // B1

        // issue W2(nc) for nc>=1 (buffer freed by B1 which retires GEMM2(nc-1))
        if (nc >= 1) {
            for (int i = tid; i < 512; i += THREADS) {
                const int row = i >> 3, seg = i & 7;
                cp16(sb + W2CH_OFF + row * PITCHB + seg * 16,
                     (const char*)g_w2h + row * 512 + nc * 128 + seg * 16);
                cp16(sb + W2CL_OFF + row * PITCHB + seg * 16,
                     (const char*)g_w2l + row * 512 + nc * 128 + seg * 16);
            }
            cp_commit();
        }

        // ===== GEMM1: C1[128 pix x 64 hid] = X * W1c^T, K = 64 =====
        float acc1[2][4][4];
        #pragma unroll
        for (int mt = 0; mt < 2; ++mt)
            #pragma unroll
            for (int nt = 0; nt < 4; ++nt)
                #pragma unroll
                for (int j = 0; j < 4; ++j) acc1[mt][nt][j] = 0.f;

        #pragma unroll
        for (int ks = 0; ks < 4; ++ks) {
            uint32_t axh[8], axl[8], bh[8], bl[8];
            LDSM4(axh[0], axh[1], axh[2], axh[3], aXbase + ks * 32);
            LDSM4(axh[4], axh[5], axh[6], axh[7], aXbase + 16 * PITCHB + ks * 32);
            LDSM4(axl[0], axl[1], axl[2], axl[3], aXbase + XLD + ks * 32);
            LDSM4(axl[4], axl[5], axl[6], axl[7], aXbase + XLD + 16 * PITCHB + ks * 32);
            LDSM4(bh[0], bh[1], bh[2], bh[3], bW1base + ks * 32);
            LDSM4(bh[4], bh[5], bh[6], bh[7], bW1base + 16 * PITCHB + ks * 32);
            #pragma unroll
            for (int mt = 0; mt < 2; ++mt)
                #pragma unroll
                for (int nt = 0; nt < 4; ++nt) {
                    mma16816(acc1[mt][nt], axh + mt * 4, bh + nt * 2);
                    mma16816(acc1[mt][nt], axl + mt * 4, bh + nt * 2);
                }
            LDSM4(bl[0], bl[1], bl[2], bl[3], bW1base + W1LD + ks * 32);
            LDSM4(bl[4], bl[5], bl[6], bl[7], bW1base + W1LD + 16 * PITCHB + ks * 32);
            #pragma unroll
            for (int mt = 0; mt < 2; ++mt)
                #pragma unroll
                for (int nt = 0; nt < 4; ++nt)
                    mma16816(acc1[mt][nt], axh + mt * 4, bl + nt * 2);
        }

        __syncthreads();                               // B2: W1c reads done

        // issue W1(nc+1)
        if (nc < 3) {
            for (int i = tid; i < 512; i += THREADS) {
                const int row = i >> 3, seg = i & 7;
                cp16(sb + W1CH_OFF + row * PITCHB + seg * 16,
                     (const char*)g_w1h + (nc + 1) * 8192 + row * 128 + seg * 16);
                cp16(sb + W1CL_OFF + row * PITCHB + seg * 16,
                     (const char*)g_w1l + (nc + 1) * 8192 + row * 128 + seg * 16);
            }
            cp_commit();
        }

        // ---- bias + exact GELU -> bf16 hi/lo -> H ----
        #pragma unroll
        for (int mt = 0; mt < 2; ++mt)
            #pragma unroll
            for (int nt = 0; nt < 4; ++nt) {
                const int nl = wcg * 32 + nt * 8 + dCol;           // 0..63
                const float bb0 = b1_s[nc * 64 + nl];
                const float bb1 = b1_s[nc * 64 + nl + 1];
                const int r0 = pr * 32 + mt * 16 + dRow;
                #pragma unroll
                for (int hh = 0; hh < 2; ++hh) {
                    const float g0 = gelu_exact(acc1[mt][nt][hh * 2 + 0] + bb0);
                    const float g1 = gelu_exact(acc1[mt][nt][hh * 2 + 1] + bb1);
                    const __nv_bfloat16 h0 = __float2bfloat16(g0);
                    const __nv_bfloat16 h1 = __float2bfloat16(g1);
                    const uint32_t o = (uint32_t)((r0 + hh * 8) * PITCHB + nl * 2);
                    *(uint32_t*)(smem + HH_OFF + o) = pbf2(h0, h1);
                    *(uint32_t*)(smem + HL_OFF + o) =
                        pbf2(__float2bfloat16(g0 - __bfloat162float(h0)),
                             __float2bfloat16(g1 - __bfloat162float(h1)));
                }
            }

        // W2(nc) must be complete (allow W1(nc+1) pending)
        if (nc < 3) cp_wait<1>(); else cp_wait<0>();
        __syncthreads();                               // B3: H + W2c visible

        // ===== GEMM2: C2[128 pix x 64 c] += H * W2c^T, K = 64 =====
        #pragma unroll
        for (int ks = 0; ks < 4; ++ks) {
            uint32_t ahh[8], ahl[8], bh[8], bl[8];
            LDSM4(ahh[0], ahh[1], ahh[2], ahh[3], aHbase + ks * 32);
            LDSM4(ahh[4], ahh[5], ahh[6], ahh[7], aHbase + 16 * PITCHB + ks * 32);
            LDSM4(ahl[0], ahl[1], ahl[2], ahl[3], aHbase + HLD + ks * 32);
            LDSM4(ahl[4], ahl[5], ahl[6], ahl[7], aHbase + HLD + 16 * PITCHB + ks * 32);
            LDSM4(bh[0], bh[1], bh[2], bh[3], bW2base + ks * 32);
            LDSM4(bh[4], bh[5], bh[6], bh[7], bW2base + 16 * PITCHB + ks * 32);
            #pragma unroll
            for (int mt = 0; mt < 2; ++mt)
                #pragma unroll
                for (int nt = 0; nt < 4; ++nt) {
                    mma16816(acc2[mt][nt], ahh + mt * 4, bh + nt * 2);
                    mma16816(acc2[mt][nt], ahl + mt * 4, bh + nt * 2);
                }
            LDSM4(bl[0], bl[1], bl[2], bl[3], bW2base + W2LD + ks * 32);
            LDSM4(bl[4], bl[5], bl[6], bl[7], bW2base + W2LD + 16 * PITCHB + ks * 32);
            #pragma unroll
            for (int mt = 0; mt < 2; ++mt)
                #pragma unroll
                for (int nt = 0; nt < 4; ++nt)
                    mma16816(acc2[mt][nt], ahh + mt * 4, bl + nt * 2);
        }
    }

    // ---- y (+bias) -> y_s (X overlay; X dead since B2(3)) ----
    float* y_s = (float*)(smem + YS_OFF);
    float* m_s = (float*)(smem + MS_OFF);

    #pragma unroll
    for (int mt = 0; mt < 2; ++mt)
        #pragma unroll
        for (int nt = 0; nt < 4; ++nt) {
            const int c0 = wcg * 32 + nt * 8 + dCol;
            const int r0 = pr * 32 + mt * 16 + dRow;
            #pragma unroll
            for (int hh = 0; hh < 2; ++hh) {
                y_s[(c0)     * X_PITCH + r0 + hh * 8] = acc2[mt][nt][hh * 2 + 0] + b2_s[c0];
                y_s[(c0 + 1) * X_PITCH + r0 + hh * 8] = acc2[mt][nt][hh * 2 + 1] + b2_s[c0 + 1];
            }
        }
    __syncthreads();                                   // B4: all GEMM2 + y done

    // ---- mix matrices -> MS overlay (H/W regions dead) via cp.async ----
    for (int i = tid; i < 4096; i += THREADS)
        cp16(sb + MS_OFF + i * 16, (const char*)g_M + i * 16);
    cp_commit();
    cp_wait<0>();
    __syncthreads();                                   // B5

    // ---- Fourier mix: 2 windows per thread ----
    const int c   = tid >> 2;          // 0..63
    const int wcb = (tid & 3) * 2;     // window col base

    #pragma unroll
    for (int jw = 0; jw < 2; ++jw) {
        const int wc = wcb + jw;
        float pin[16];
        #pragma unroll
        for (int r4 = 0; r4 < 4; ++r4) {
            const float4 v = *(const float4*)&y_s[c * X_PITCH + r4 * 32 + wc * 4];
            pin[r4 * 4 + 0] = v.x; pin[r4 * 4 + 1] = v.y;
            pin[r4 * 4 + 2] = v.z; pin[r4 * 4 + 3] = v.w;
        }
        float po[16];
        const float* mrow = &m_s[c * 256];
        #pragma unroll
        for (int o = 0; o < 16; ++o) {
            float s = 0.f;
            #pragma unroll
            for (int i4 = 0; i4 < 4; ++i4) {
                const float4 mv = *(const float4*)&mrow[o * 16 + i4 * 4];
                s += mv.x * pin[i4 * 4 + 0];
                s += mv.y * pin[i4 * 4 + 1];
                s += mv.z * pin[i4 * 4 + 2];
                s += mv.w * pin[i4 * 4 + 3];
            }
            po[o] = s;
        }
        const size_t obase = (((size_t)b * C_IN + c) * H_SZ + h0) * W_SZ + w0 + wc * 4;
        #pragma unroll
        for (int r4 = 0; r4 < 4; ++r4) {
            *(float4*)&out[obase + (size_t)r4 * W_SZ] =
                make_float4(po[r4 * 4 + 0], po[r4 * 4 + 1], po[r4 * 4 + 2], po[r4 * 4 + 3]);
        }
    }
}

// ---------------------------------------------------------------------------
extern "C" void kernel_launch(void* const* d_in, const int* in_sizes, int n_in,
                              void* d_out, int out_size) {
    const float* x  = (const float*)d_in[0];
    const float* w1 = (const float*)d_in[1];
    const float* b1 = (const float*)d_in[2];
    const float* w2 = (const float*)d_in[3];
    const float* b2 = (const float*)d_in[4];
    const float* cw = (const float*)d_in[5];
    float* out = (float*)d_out;

    cudaFuncSetAttribute(fmffn_kernel,
                         cudaFuncAttributeMaxDynamicSharedMemorySize, SMEM_BYTES);

    build_mix_kernel<<<64, 256>>>(cw);
    build_weights_kernel<<<128, 256>>>(w1, w2);

    dim3 grid(W_SZ / 32, H_SZ / 4, B_SZ);   // (8, 64, 8)
    fmffn_kernel<<<grid, THREADS, SMEM_BYTES>>>(x, b1, b2, out);
}

// round 9
// speedup vs baseline: 4.3215x; 1.2814x over previous
#include <cuda_runtime.h>
#include <cuda_fp16.h>
#include <math.h>
#include <stdint.h>

#define B_SZ   8
#define C_IN   64
#define HID    256
#define H_SZ   256
#define W_SZ   256
#define THREADS 256
#define NH     32           // hid chunk
#define NCHUNK 8

// pitches (bytes)
#define XPB  144            // 64 c fp16 = 128B + 16 pad
#define HPB  80             // 32 hid fp16 = 64B + 16 pad
#define W1PB 144            // 64 c fp16
#define W2PB 80             // 32 hid fp16

// ---------------- smem layout (bytes) ----------------
#define X_OFF    0          // 128 x 144 = 18432
#define H_OFF    18432      // 128 x 80  = 10240
#define W1H_OFF  28672      // 32 x 144  = 4608
#define W1L_OFF  33280      // 4608
#define W2H_OFF  37888      // 64 x 80   = 5120
#define W2L_OFF  43008      // 5120
#define B1S_OFF  48128      // 256 f32
#define B2S_OFF  49152      // 64 f32
#define SMEM_BYTES 49408

// final-stage overlay (X+H+W1 regions, all dead after the loop)
#define YS_OFF  0           // 64 x 132 f32 = 33792
#define X_PITCH 132

// ---------------------------------------------------------------------------
__device__ __forceinline__ uint32_t smem_u32(const void* p) {
    uint32_t a;
    asm("{ .reg .u64 t; cvta.to.shared.u64 t, %1; cvt.u32.u64 %0, t; }" : "=r"(a) : "l"(p));
    return a;
}

#define LDSM4(r0, r1, r2, r3, addr) \
    asm volatile("ldmatrix.sync.aligned.m8n8.x4.shared.b16 {%0,%1,%2,%3}, [%4];" \
        : "=r"(r0), "=r"(r1), "=r"(r2), "=r"(r3) : "r"(addr))

__device__ __forceinline__ void mma16816(float* d, const uint32_t* a, const uint32_t* b) {
    asm volatile(
        "mma.sync.aligned.m16n8k16.row.col.f32.f16.f16.f32 "
        "{%0,%1,%2,%3}, {%4,%5,%6,%7}, {%8,%9}, {%0,%1,%2,%3};"
        : "+f"(d[0]), "+f"(d[1]), "+f"(d[2]), "+f"(d[3])
        : "r"(a[0]), "r"(a[1]), "r"(a[2]), "r"(a[3]), "r"(b[0]), "r"(b[1]));
}

__device__ __forceinline__ void cp16(uint32_t dst, const void* src) {
    asm volatile("cp.async.cg.shared.global [%0], [%1], 16;"
                 :: "r"(dst), "l"(__cvta_generic_to_global(src)) : "memory");
}
__device__ __forceinline__ void cp_commit() {
    asm volatile("cp.async.commit_group;" ::: "memory");
}
template <int N>
__device__ __forceinline__ void cp_wait() {
    asm volatile("cp.async.wait_group %0;" :: "n"(N) : "memory");
}

__device__ __forceinline__ uint32_t ph2(__half a, __half b) {
    uint32_t r;
    asm("mov.b32 %0, {%1, %2};" : "=r"(r)
        : "h"(__half_as_ushort(a)), "h"(__half_as_ushort(b)));
    return r;
}

__device__ __forceinline__ float gelu_exact(float x) {
    return 0.5f * x * (1.f + erff(x * 0.70710678118654752440f));
}

// ---------------------------------------------------------------------------
// Precomputed global scratch
// ---------------------------------------------------------------------------
__device__ float g_M[64 * 256];
__device__ __half g_w1h[HID * C_IN], g_w1l[HID * C_IN];
__device__ __half g_w2h[C_IN * HID], g_w2l[C_IN * HID];

__global__ void build_mix_kernel(const float* __restrict__ cw) {
    const int c   = blockIdx.x;
    const int t   = threadIdx.x;
    const int in  = t >> 4;
    const int out = t & 15;
    const int s  = in >> 2, tt = in & 3;
    const int p  = out >> 2, q  = out & 3;
    const float cs[4] = {1.f, 0.f, -1.f, 0.f};
    const float sn[4] = {0.f, 1.f, 0.f, -1.f};
    float tre[3] = {0.f, 0.f, 0.f};
    float tim[3] = {0.f, 0.f, 0.f};
    #pragma unroll
    for (int u = 0; u < 4; ++u) {
        const int e2 = (u * p) & 3;
        const float c2 = cs[e2], s2 = sn[e2];
        #pragma unroll
        for (int v = 0; v < 3; ++v) {
            const int e1 = (4 - ((u * s + v * tt) & 3)) & 3;
            const float yr = 0.25f * cs[e1];
            const float yi = 0.25f * sn[e1];
            const float wr = cw[((u * 3 + v) * 64 + c) * 2 + 0];
            const float wi = cw[((u * 3 + v) * 64 + c) * 2 + 1];
            const float zr = yr * wr - yi * wi;
            const float zi = yr * wi + yi * wr;
            tre[v] += zr * c2 - zi * s2;
            tim[v] += zr * s2 + zi * c2;
        }
    }
    const float sgn = (q & 1) ? -1.f : 1.f;
    g_M[c * 256 + out * 16 + in] =
        0.25f * (tre[0] + sgn * tre[2] + 2.f * (tre[1] * cs[q] - tim[1] * sn[q]));
}

__global__ void build_weights_kernel(const float* __restrict__ w1,
                                     const float* __restrict__ w2) {
    const int i = blockIdx.x * blockDim.x + threadIdx.x;   // 0..32767
    if (i < HID * C_IN) {
        const float v = w1[i];
        const __half hi = __float2half_rn(v);
        g_w1h[i] = hi;
        g_w1l[i] = __float2half_rn(v - __half2float(hi));
    } else {
        const int j = i - HID * C_IN;
        const float v = w2[j];
        const __half hi = __float2half_rn(v);
        g_w2h[j] = hi;
        g_w2l[j] = __float2half_rn(v - __half2float(hi));
    }
}

// ---------------------------------------------------------------------------
// Main kernel: fp16 activations + split-fp16 weights, occupancy 3
// ---------------------------------------------------------------------------
__global__ __launch_bounds__(THREADS, 3)
void fmffn_kernel(const float* __restrict__ x,
                  const float* __restrict__ b1,
                  const float* __restrict__ b2,
                  float* __restrict__ out) {
    extern __shared__ char smem[];
    const uint32_t sb = smem_u32(smem);

    const int tid  = threadIdx.x;
    const int wid  = tid >> 5;
    const int lane = tid & 31;
    const int b    = blockIdx.z;
    const int h0   = blockIdx.y * 4;
    const int w0   = blockIdx.x * 32;

    float* b1_s = (float*)(smem + B1S_OFF);
    float* b2_s = (float*)(smem + B2S_OFF);

    // per-thread cp.async coordinates
    const int w1row = tid >> 3, w1seg = tid & 7;     // 32 x 8
    const int w2row = tid >> 2, w2seg = tid & 3;     // 64 x 4

    // ---- prefetch chunk 0: W1 group, then W2 group ----
    cp16(sb + W1H_OFF + w1row * W1PB + w1seg * 16, g_w1h + w1row * 64 + w1seg * 8);
    cp16(sb + W1L_OFF + w1row * W1PB + w1seg * 16, g_w1l + w1row * 64 + w1seg * 8);
    cp_commit();
    cp16(sb + W2H_OFF + w2row * W2PB + w2seg * 16, g_w2h + w2row * 256 + w2seg * 8);
    cp16(sb + W2L_OFF + w2row * W2PB + w2seg * 16, g_w2l + w2row * 256 + w2seg * 8);
    cp_commit();

    // ---- stage x -> fp16 [pix][c] ----
    for (int i = tid; i < 64 * 128; i += THREADS) {
        const int c = i >> 7, pix = i & 127;
        const int r = pix >> 5, col = pix & 31;
        const float v = x[(((size_t)b * C_IN + c) * H_SZ + (h0 + r)) * W_SZ + (w0 + col)];
        *(__half*)(smem + X_OFF + pix * XPB + c * 2) = __float2half_rn(v);
    }
    if (tid < HID)  b1_s[tid] = b1[tid];
    if (tid < C_IN) b2_s[tid] = b2[tid];

    // ---- warp geometry ----
    const int pr  = wid & 3;              // pixel group (32 pix)
    const int wcg = wid >> 2;             // n group
    const int aRow = (lane & 7) + ((lane >> 3) & 1) * 8;
    const int aKof = (lane >> 4) * 8;
    const int bRow = (lane & 7) + (lane >> 4) * 8;
    const int bKof = ((lane >> 3) & 1) * 8;
    const int dRow = lane >> 2;
    const int dCol = (lane & 3) * 2;

    const uint32_t aXbase  = sb + X_OFF   + (uint32_t)((pr * 32 + aRow) * XPB + aKof * 2);
    const uint32_t aHbase  = sb + H_OFF   + (uint32_t)((pr * 32 + aRow) * HPB + aKof * 2);
    const uint32_t bW1base = sb + W1H_OFF + (uint32_t)((wcg * 16 + bRow) * W1PB + bKof * 2);
    const uint32_t bW2base = sb + W2H_OFF + (uint32_t)((wcg * 32 + bRow) * W2PB + bKof * 2);
#define W1LD (W1L_OFF - W1H_OFF)
#define W2LD (W2L_OFF - W2H_OFF)

    // persistent GEMM2 accumulators: 32 pix x 32 c per warp
    float acc2[2][4][4];
    #pragma unroll
    for (int mt = 0; mt < 2; ++mt)
        #pragma unroll
        for (int nt = 0; nt < 4; ++nt)
            #pragma unroll
            for (int j = 0; j < 4; ++j) acc2[mt][nt][j] = 0.f;

    // ---- 8 hid chunks of 32 ----
    #pragma unroll 1
    for (int nc = 0; nc < NCHUNK; ++nc) {
        cp_wait<0>();
        __syncthreads();                               // B1

        if (nc >= 1) {                                 // W2(nc): buffer freed by B1
            cp16(sb + W2H_OFF + w2row * W2PB + w2seg * 16,
                 g_w2h + w2row * 256 + nc * NH + w2seg * 8);
            cp16(sb + W2L_OFF + w2row * W2PB + w2seg * 16,
                 g_w2l + w2row * 256 + nc * NH + w2seg * 8);
            cp_commit();
        }

        // ===== GEMM1: [128 pix x 32 hid], K = 64, warp tile 32x16 =====
        float acc1[2][2][4];
        #pragma unroll
        for (int mt = 0; mt < 2; ++mt)
            #pragma unroll
            for (int nt = 0; nt < 2; ++nt)
                #pragma unroll
                for (int j = 0; j < 4; ++j) acc1[mt][nt][j] = 0.f;

        #pragma unroll
        for (int ks = 0; ks < 4; ++ks) {
            uint32_t ax[8], bh[4], bl[4];
            LDSM4(ax[0], ax[1], ax[2], ax[3], aXbase + ks * 32);
            LDSM4(ax[4], ax[5], ax[6], ax[7], aXbase + 16 * XPB + ks * 32);
            LDSM4(bh[0], bh[1], bh[2], bh[3], bW1base + ks * 32);
            LDSM4(bl[0], bl[1], bl[2], bl[3], bW1base + W1LD + ks * 32);
            #pragma unroll
            for (int mt = 0; mt < 2; ++mt)
                #pragma unroll
                for (int nt = 0; nt < 2; ++nt) {
                    mma16816(acc1[mt][nt], ax + mt * 4, bh + nt * 2);
                    mma16816(acc1[mt][nt], ax + mt * 4, bl + nt * 2);
                }
        }

        __syncthreads();                               // B2: W1c reads done

        if (nc < NCHUNK - 1) {                         // W1(nc+1)
            cp16(sb + W1H_OFF + w1row * W1PB + w1seg * 16,
                 g_w1h + (nc + 1) * NH * 64 + w1row * 64 + w1seg * 8);
            cp16(sb + W1L_OFF + w1row * W1PB + w1seg * 16,
                 g_w1l + (nc + 1) * NH * 64 + w1row * 64 + w1seg * 8);
            cp_commit();
        }

        // ---- bias + exact GELU -> fp16 -> H ----
        #pragma unroll
        for (int mt = 0; mt < 2; ++mt)
            #pragma unroll
            for (int nt = 0; nt < 2; ++nt) {
                const int nl = wcg * 16 + nt * 8 + dCol;           // 0..31
                const float bb0 = b1_s[nc * NH + nl];
                const float bb1 = b1_s[nc * NH + nl + 1];
                const int r0 = pr * 32 + mt * 16 + dRow;
                #pragma unroll
                for (int hh = 0; hh < 2; ++hh) {
                    const float g0 = gelu_exact(acc1[mt][nt][hh * 2 + 0] + bb0);
                    const float g1 = gelu_exact(acc1[mt][nt][hh * 2 + 1] + bb1);
                    *(uint32_t*)(smem + H_OFF + (r0 + hh * 8) * HPB + nl * 2) =
                        ph2(__float2half_rn(g0), __float2half_rn(g1));
                }
            }

        if (nc < NCHUNK - 1) cp_wait<1>(); else cp_wait<0>();   // W2(nc) complete
        __syncthreads();                               // B3: H + W2c visible

        // ===== GEMM2: [128 pix x 64 c] += H * W2c^T, K = 32, warp 32x32 =====
        #pragma unroll
        for (int ks = 0; ks < 2; ++ks) {
            uint32_t ah[8], bh[8], bl[8];
            LDSM4(ah[0], ah[1], ah[2], ah[3], aHbase + ks * 32);
            LDSM4(ah[4], ah[5], ah[6], ah[7], aHbase + 16 * HPB + ks * 32);
            LDSM4(bh[0], bh[1], bh[2], bh[3], bW2base + ks * 32);
            LDSM4(bh[4], bh[5], bh[6], bh[7], bW2base + 16 * W2PB + ks * 32);
            LDSM4(bl[0], bl[1], bl[2], bl[3], bW2base + W2LD + ks * 32);
            LDSM4(bl[4], bl[5], bl[6], bl[7], bW2base + W2LD + 16 * W2PB + ks * 32);
            #pragma unroll
            for (int mt = 0; mt < 2; ++mt)
                #pragma unroll
                for (int nt = 0; nt < 4; ++nt) {
                    mma16816(acc2[mt][nt], ah + mt * 4, bh + nt * 2);
                    mma16816(acc2[mt][nt], ah + mt * 4, bl + nt * 2);
                }
        }
    }

    __syncthreads();                                   // B4: all reads of X/H/W done

    // ---- y (+bias) -> y_s overlay ----
    float* y_s = (float*)(smem + YS_OFF);
    #pragma unroll
    for (int mt = 0; mt < 2; ++mt)
        #pragma unroll
        for (int nt = 0; nt < 4; ++nt) {
            const int c0 = wcg * 32 + nt * 8 + dCol;
            const int r0 = pr * 32 + mt * 16 + dRow;
            #pragma unroll
            for (int hh = 0; hh < 2; ++hh) {
                y_s[(c0)     * X_PITCH + r0 + hh * 8] = acc2[mt][nt][hh * 2 + 0] + b2_s[c0];
                y_s[(c0 + 1) * X_PITCH + r0 + hh * 8] = acc2[mt][nt][hh * 2 + 1] + b2_s[c0 + 1];
            }
        }
    __syncthreads();                                   // B5

    // ---- Fourier mix: 2 windows per thread; M from global (L1-resident) ----
    const int c   = tid >> 2;          // 0..63
    const int wcb = (tid & 3) * 2;
    const float4* mrow = (const float4*)(g_M + c * 256);

    #pragma unroll
    for (int jw = 0; jw < 2; ++jw) {
        const int wc = wcb + jw;
        float pin[16];
        #pragma unroll
        for (int r4 = 0; r4 < 4; ++r4) {
            const float4 v = *(const float4*)&y_s[c * X_PITCH + r4 * 32 + wc * 4];
            pin[r4 * 4 + 0] = v.x; pin[r4 * 4 + 1] = v.y;
            pin[r4 * 4 + 2] = v.z; pin[r4 * 4 + 3] = v.w;
        }
        float po[16];
        #pragma unroll
        for (int o = 0; o < 16; ++o) {
            const float4 m0 = __ldg(mrow + o * 4 + 0);
            const float4 m1 = __ldg(mrow + o * 4 + 1);
            const float4 m2 = __ldg(mrow + o * 4 + 2);
            const float4 m3 = __ldg(mrow + o * 4 + 3);
            float s = m0.x * pin[0] + m0.y * pin[1] + m0.z * pin[2] + m0.w * pin[3];
            s += m1.x * pin[4]  + m1.y * pin[5]  + m1.z * pin[6]  + m1.w * pin[7];
            s += m2.x * pin[8]  + m2.y * pin[9]  + m2.z * pin[10] + m2.w * pin[11];
            s += m3.x * pin[12] + m3.y * pin[13] + m3.z * pin[14] + m3.w * pin[15];
            po[o] = s;
        }
        const size_t obase = (((size_t)b * C_IN + c) * H_SZ + h0) * W_SZ + w0 + wc * 4;
        #pragma unroll
        for (int r4 = 0; r4 < 4; ++r4) {
            *(float4*)&out[obase + (size_t)r4 * W_SZ] =
                make_float4(po[r4 * 4 + 0], po[r4 * 4 + 1], po[r4 * 4 + 2], po[r4 * 4 + 3]);
        }
    }
}

// ---------------------------------------------------------------------------
extern "C" void kernel_launch(void* const* d_in, const int* in_sizes, int n_in,
                              void* d_out, int out_size) {
    const float* x  = (const float*)d_in[0];
    const float* w1 = (const float*)d_in[1];
    const float* b1 = (const float*)d_in[2];
    const float* w2 = (const float*)d_in[3];
    const float* b2 = (const float*)d_in[4];
    const float* cw = (const float*)d_in[5];
    float* out = (float*)d_out;

    cudaFuncSetAttribute(fmffn_kernel,
                         cudaFuncAttributeMaxDynamicSharedMemorySize, SMEM_BYTES);

    build_mix_kernel<<<64, 256>>>(cw);
    build_weights_kernel<<<128, 256>>>(w1, w2);

    dim3 grid(W_SZ / 32, H_SZ / 4, B_SZ);   // (8, 64, 8)
    fmffn_kernel<<<grid, THREADS, SMEM_BYTES>>>(x, b1, b2, out);
}